// round 14
// baseline (speedup 1.0000x reference)
#include <cuda_runtime.h>
#include <cuda_bf16.h>
#include <math.h>
#include <stdint.h>

#define NTOK 4096
#define NPAD 4097
#define TPADN 4224          // 33*128, padded token count for mma tiles
#define DIM 512
#define HEADS 8
#define DH 64
#define MM 17
#define LBLK 241
#define QKVD 1536
#define KCONV 33
#define OUT1_SIZE (NTOK*DIM)
#define ATTN_PER_HEAD ((size_t)NPAD*NPAD)
#define AVCH 16
#define AVCHUNK ((NPAD + AVCH - 1)/AVCH)   // 257

// ---------------- scratch ---------------------------------------------------
__device__ float g_qkv[NPAD*QKVD];
__device__ float g_ql[HEADS*MM*DH];
__device__ float g_kl[HEADS*MM*DH];
__device__ float g_attn3[HEADS*MM*NPAD];
__device__ float g_inv[HEADS*MM*MM];
__device__ float g_avp[AVCH*HEADS*MM*DH];
__device__ float g_w1[HEADS*NPAD*MM];
// bf16 2-way splits (hi, mid)
__device__ __nv_bfloat16 g_ah[NPAD*DIM], g_am[NPAD*DIM];
__device__ __nv_bfloat16 g_oh[NPAD*DIM], g_om[NPAD*DIM];
__device__ __nv_bfloat16 g_wqh[QKVD*DIM], g_wqm[QKVD*DIM];
__device__ __nv_bfloat16 g_woh[DIM*DIM], g_wom[DIM*DIM];
// attn-final mma operands: k 0..15 as bf16 splits, k=16 as fp32
__device__ __nv_bfloat16 g_fw1h[HEADS*TPADN*16], g_fw1m[HEADS*TPADN*16];
__device__ __nv_bfloat16 g_fa3h[HEADS*TPADN*16], g_fa3m[HEADS*TPADN*16];
__device__ float g_w1c16[HEADS*TPADN];
__device__ float g_a3r16[HEADS*TPADN];

__device__ __forceinline__ uint32_t s2u(const void* p) {
    return (uint32_t)__cvta_generic_to_shared(p);
}
__device__ __forceinline__ void split2(float x, __nv_bfloat16& h, __nv_bfloat16& m) {
    h = __float2bfloat16(x);
    float r1 = x - __bfloat162float(h);
    m = __float2bfloat16(r1);
}

// ---------------- 1. LayerNorm -> split bf16 ---------------------------------
__global__ void ln_kernel(const float* __restrict__ x,
                          const float* __restrict__ w,
                          const float* __restrict__ b) {
    int r = blockIdx.x;
    int tid = threadIdx.x;
    if (r == 0) {
        __nv_bfloat16 z = __float2bfloat16(0.f);
        for (int c = tid; c < DIM; c += 256) { g_ah[c]=z; g_am[c]=z; }
        return;
    }
    const float* row = x + (size_t)(r-1)*DIM;
    __shared__ float red[256];
    float s = 0.f;
    for (int c = tid; c < DIM; c += 256) s += row[c];
    red[tid] = s; __syncthreads();
    for (int o = 128; o; o >>= 1) { if (tid < o) red[tid] += red[tid+o]; __syncthreads(); }
    float mu = red[0] * (1.0f/DIM);
    __syncthreads();
    float v = 0.f;
    for (int c = tid; c < DIM; c += 256) { float d = row[c]-mu; v += d*d; }
    red[tid] = v; __syncthreads();
    for (int o = 128; o; o >>= 1) { if (tid < o) red[tid] += red[tid+o]; __syncthreads(); }
    float rs = rsqrtf(red[0]*(1.0f/DIM) + 1e-5f);
    for (int c = tid; c < DIM; c += 256) {
        float val = (row[c]-mu)*rs*w[c] + b[c];
        __nv_bfloat16 h, m;
        split2(val, h, m);
        size_t idx = (size_t)r*DIM + c;
        g_ah[idx]=h; g_am[idx]=m;
    }
}

// ---------------- weight split (both matrices, one launch) --------------------
#define NWQ (QKVD*DIM)
#define NWO (DIM*DIM)
__global__ void wcvt_kernel(const float* __restrict__ wq, const float* __restrict__ wo) {
    int i = blockIdx.x*256 + threadIdx.x;
    if (i < NWQ) {
        split2(wq[i], g_wqh[i], g_wqm[i]);
    } else if (i < NWQ + NWO) {
        int j = i - NWQ;
        split2(wo[j], g_woh[j], g_wom[j]);
    }
}

// ---------------- mma.sync bf16 GEMM: C = A(MxK) @ B^T ------------------------
#define TPAD 40
#define TILE_B (128*TPAD*2)      // 10240 bytes per tile
#define STAGE_B (4*TILE_B)       // 40960
#define GSMEM (2*STAGE_B)        // 81920 (2 stages -> 2 CTAs/SM)

__device__ __forceinline__ void cp16(uint32_t daddr, const void* g, int sz) {
    asm volatile("cp.async.ca.shared.global [%0], [%1], 16, %2;"
                 :: "r"(daddr), "l"(g), "r"(sz));
}
__device__ __forceinline__ void ldm4(uint32_t* r, uint32_t addr) {
    asm volatile("ldmatrix.sync.aligned.m8n8.x4.shared.b16 {%0,%1,%2,%3}, [%4];"
                 : "=r"(r[0]), "=r"(r[1]), "=r"(r[2]), "=r"(r[3]) : "r"(addr));
}
__device__ __forceinline__ void mma16816(float* c, const uint32_t* a, const uint32_t* b) {
    asm volatile("mma.sync.aligned.m16n8k16.row.col.f32.bf16.bf16.f32 "
                 "{%0,%1,%2,%3}, {%4,%5,%6,%7}, {%8,%9}, {%0,%1,%2,%3};"
                 : "+f"(c[0]), "+f"(c[1]), "+f"(c[2]), "+f"(c[3])
                 : "r"(a[0]), "r"(a[1]), "r"(a[2]), "r"(a[3]), "r"(b[0]), "r"(b[1]));
}

__global__ __launch_bounds__(256, 2)
void gemm_mma(const __nv_bfloat16* __restrict__ a0, const __nv_bfloat16* __restrict__ a1,
              const __nv_bfloat16* __restrict__ b0, const __nv_bfloat16* __restrict__ b1,
              float* __restrict__ C, int M, int N, int K, int mode,
              const float* __restrict__ bias, const float* __restrict__ resid) {
    extern __shared__ char smem[];
    uint32_t sbase = s2u(smem);
    int tid = threadIdx.x, lane = tid & 31, wid = tid >> 5;
    int warp_m = wid & 3, warp_n = wid >> 2;
    int m0 = blockIdx.y * 128, n0 = blockIdx.x * 128;
    const __nv_bfloat16* asrc[2] = {a0, a1};
    const __nv_bfloat16* bsrc[2] = {b0, b1};

    int ldrow = tid >> 2, ldc4 = tid & 3;
    float acc[2][8][4];
    #pragma unroll
    for (int i = 0; i < 2; i++)
        #pragma unroll
        for (int j = 0; j < 8; j++)
            #pragma unroll
            for (int v = 0; v < 4; v++) acc[i][j][v] = 0.f;

    int nchunks = K / 32;

    auto stage = [&](int chunk, int buf) {
        int k0 = chunk * 32;
        uint32_t stb = sbase + buf*STAGE_B;
        #pragma unroll
        for (int s = 0; s < 4; s++) {
            const __nv_bfloat16* src = (s < 2) ? asrc[s] : bsrc[s-2];
            int base = (s < 2) ? m0 : n0;
            uint32_t tb = stb + s*TILE_B;
            #pragma unroll
            for (int i = 0; i < 2; i++) {
                int row = ldrow + i*64;
                int gr = base + row;
                int ok = (s >= 2) || (gr < M);
                int grc = ok ? gr : 0;
                cp16(tb + row*80 + ldc4*16, src + (size_t)grc*K + k0 + ldc4*8, ok ? 16 : 0);
            }
        }
        asm volatile("cp.async.commit_group;");
    };

    stage(0, 0);

    int arow = warp_m*32 + (lane & 15);
    int akoff = ((lane >> 4) << 3);
    int brow = warp_n*64 + (lane & 7) + ((lane >> 4) << 3);
    int bkoff = ((lane >> 3) & 1) << 3;

    for (int c = 0; c < nchunks; c++) {
        if (c + 1 < nchunks) {
            stage(c + 1, (c + 1) & 1);
            asm volatile("cp.async.wait_group 1;");
        } else {
            asm volatile("cp.async.wait_group 0;");
        }
        __syncthreads();
        uint32_t stb = sbase + (c & 1)*STAGE_B;
        #pragma unroll
        for (int k16 = 0; k16 < 2; k16++) {
            uint32_t afr[2][2][4];
            #pragma unroll
            for (int s = 0; s < 2; s++)
                #pragma unroll
                for (int mi = 0; mi < 2; mi++)
                    ldm4(afr[s][mi], stb + s*TILE_B + (arow + mi*16)*80 + (akoff + k16*16)*2);
            #pragma unroll
            for (int g = 0; g < 4; g++) {
                uint32_t bh[4], bm[4];
                ldm4(bh, stb + 2*TILE_B + (brow + g*16)*80 + (bkoff + k16*16)*2);
                ldm4(bm, stb + 3*TILE_B + (brow + g*16)*80 + (bkoff + k16*16)*2);
                #pragma unroll
                for (int mi = 0; mi < 2; mi++) {
                    mma16816(acc[mi][2*g],   afr[0][mi], bh);
                    mma16816(acc[mi][2*g],   afr[0][mi], bm);
                    mma16816(acc[mi][2*g],   afr[1][mi], bh);
                    mma16816(acc[mi][2*g+1], afr[0][mi], bh+2);
                    mma16816(acc[mi][2*g+1], afr[0][mi], bm+2);
                    mma16816(acc[mi][2*g+1], afr[1][mi], bh+2);
                }
            }
        }
        __syncthreads();
    }

    // ---- epilogue
    int g = lane >> 2, tg = lane & 3;
    #pragma unroll
    for (int mi = 0; mi < 2; mi++) {
        #pragma unroll
        for (int nj = 0; nj < 8; nj++) {
            int col = n0 + warp_n*64 + nj*8 + tg*2;
            int r0 = m0 + warp_m*32 + mi*16 + g;
            int r1 = r0 + 8;
            float v0 = acc[mi][nj][0], v1 = acc[mi][nj][1];
            float v2 = acc[mi][nj][2], v3 = acc[mi][nj][3];
            if (mode == 0) {
                if (col < 512) { v0 *= 0.125f; v1 *= 0.125f; v2 *= 0.125f; v3 *= 0.125f; }
                if (r0 < M) { C[(size_t)r0*N + col] = v0; C[(size_t)r0*N + col + 1] = v1; }
                if (r1 < M) { C[(size_t)r1*N + col] = v2; C[(size_t)r1*N + col + 1] = v3; }
            } else {
                float bb0 = bias[col], bb1 = bias[col+1];
                if (r0 < M) {
                    size_t o = (size_t)r0*N + col;
                    C[o]   = v0 + bb0 + resid[o];
                    C[o+1] = v1 + bb1 + resid[o+1];
                }
                if (r1 < M) {
                    size_t o = (size_t)r1*N + col;
                    C[o]   = v2 + bb0 + resid[o];
                    C[o+1] = v3 + bb1 + resid[o+1];
                }
            }
        }
    }
}

// ---------------- 3. landmarks ------------------------------------------------
__global__ void landmark_kernel() {
    int m = blockIdx.x, which = blockIdx.y;
    int c = threadIdx.x;
    int base = which ? 512 : 0;
    const float* p = g_qkv + (size_t)(m*LBLK)*QKVD + base + c;
    float s = 0.f;
    for (int i = 0; i < LBLK; i++) s += p[(size_t)i*QKVD];
    float v = s * (1.0f/LBLK);
    int h = c >> 6, d = c & 63;
    if (which) g_kl[(h*MM+m)*DH + d] = v; else g_ql[(h*MM+m)*DH + d] = v;
}

// ---------------- 5. attn2 softmax + pinv --------------------------------------
__global__ void pinv_kernel() {
    int h = blockIdx.x;
    int tid = threadIdx.x;          // 289
    int i = tid / MM, j = tid % MM;
    __shared__ float a[MM][MM], zz[2][MM][MM], az[MM][MM], t2[MM][MM], t3[MM][MM];
    __shared__ float sc;
    {
        const float* ql = g_ql + (h*MM + i)*DH;
        const float* kl = g_kl + (h*MM + j)*DH;
        float s = 0.f;
        #pragma unroll
        for (int d = 0; d < DH; d++) s += ql[d]*kl[d];
        a[i][j] = s;
    }
    __syncthreads();
    if (tid < MM) {
        float mx = -INFINITY;
        for (int c = 0; c < MM; c++) mx = fmaxf(mx, a[tid][c]);
        float s = 0.f;
        for (int c = 0; c < MM; c++) { float e = expf(a[tid][c]-mx); a[tid][c] = e; s += e; }
        float inv = 1.f/s;
        for (int c = 0; c < MM; c++) a[tid][c] *= inv;
    }
    __syncthreads();
    if (tid == 0) {
        float col = 0.f, row = 0.f;
        for (int r = 0; r < MM; r++) { float s = 0.f; for (int c = 0; c < MM; c++) s += fabsf(a[r][c]); col = fmaxf(col, s); }
        for (int c = 0; c < MM; c++) { float s = 0.f; for (int r = 0; r < MM; r++) s += fabsf(a[r][c]); row = fmaxf(row, s); }
        sc = 1.f/(col*row);
    }
    __syncthreads();
    int zc = 0;
    zz[0][i][j] = a[j][i] * sc;
    __syncthreads();
    for (int it = 0; it < 6; it++) {
        float s = 0.f;
        for (int k = 0; k < MM; k++) s += a[i][k]*zz[zc][k][j];
        az[i][j] = s; __syncthreads();
        s = 0.f;
        for (int k = 0; k < MM; k++) s += az[i][k]*((k==j ? 7.f : 0.f) - az[k][j]);
        t2[i][j] = (i==j ? 15.f : 0.f) - s; __syncthreads();
        s = 0.f;
        for (int k = 0; k < MM; k++) s += az[i][k]*t2[k][j];
        t3[i][j] = (i==j ? 13.f : 0.f) - s; __syncthreads();
        s = 0.f;
        for (int k = 0; k < MM; k++) s += zz[zc][i][k]*t3[k][j];
        zz[1-zc][i][j] = 0.25f*s; zc ^= 1; __syncthreads();
    }
    g_inv[(h*MM + i)*MM + j] = zz[zc][i][j];
}

// ---------------- 4+8a fused: w1 = softmax(q @ kl^T) @ inv ----------------------
// Also emits attn-final operands: g_fw1h/m + g_w1c16, zero-filling TPADN pad.
#define QS 68
__global__ __launch_bounds__(128)
void attn1w1_kernel() {
    int h = blockIdx.y;
    int t0 = blockIdx.x * 128;
    int tid = threadIdx.x;
    __shared__ float qs[128][QS];
    __shared__ float kls[MM*DH];
    __shared__ float invs[MM*MM];
    #pragma unroll
    for (int i = 0; i < 16; i++) {
        int idx = i*128 + tid;
        int row = idx >> 4, c4 = idx & 15;
        int gt = t0 + row;
        float4 v = (gt < NPAD) ? *(const float4*)&g_qkv[(size_t)gt*QKVD + h*DH + c4*4]
                               : make_float4(0,0,0,0);
        *(float4*)&qs[row][c4*4] = v;
    }
    for (int idx = tid; idx < MM*DH; idx += 128) kls[idx] = g_kl[h*MM*DH + idx];
    for (int idx = tid; idx < MM*MM; idx += 128) invs[idx] = g_inv[h*MM*MM + idx];
    __syncthreads();
    int t = t0 + tid;
    size_t fidx = (size_t)h*TPADN + t;
    if (t >= NPAD) {
        uint4 z = make_uint4(0,0,0,0);
        *(uint4*)(g_fw1h + fidx*16)     = z;
        *(uint4*)(g_fw1h + fidx*16 + 8) = z;
        *(uint4*)(g_fw1m + fidx*16)     = z;
        *(uint4*)(g_fw1m + fidx*16 + 8) = z;
        g_w1c16[fidx] = 0.f;
        return;
    }
    float lg[MM];
    #pragma unroll
    for (int m = 0; m < MM; m++) lg[m] = 0.f;
    #pragma unroll
    for (int d4 = 0; d4 < 16; d4++) {
        float4 q4 = *(const float4*)&qs[tid][d4*4];
        #pragma unroll
        for (int m = 0; m < MM; m++) {
            float4 k4 = *(const float4*)&kls[m*DH + d4*4];
            lg[m] += q4.x*k4.x + q4.y*k4.y + q4.z*k4.z + q4.w*k4.w;
        }
    }
    float mx = lg[0];
    #pragma unroll
    for (int m = 1; m < MM; m++) mx = fmaxf(mx, lg[m]);
    float sum = 0.f;
    #pragma unroll
    for (int m = 0; m < MM; m++) { lg[m] = expf(lg[m]-mx); sum += lg[m]; }
    float inv = 1.f/sum;
    #pragma unroll
    for (int m = 0; m < MM; m++) lg[m] *= inv;
    float* wout = g_w1 + ((size_t)h*NPAD + t)*MM;
    __nv_bfloat16 sh[16], smd[16];
    float c16 = 0.f;
    #pragma unroll
    for (int j = 0; j < MM; j++) {
        float s = 0.f;
        #pragma unroll
        for (int k = 0; k < MM; k++) s += lg[k]*invs[k*MM + j];
        wout[j] = s;
        if (j < 16) split2(s, sh[j], smd[j]);
        else c16 = s;
    }
    #pragma unroll
    for (int j = 0; j < 16; j++) {
        g_fw1h[fidx*16 + j] = sh[j];
        g_fw1m[fidx*16 + j] = smd[j];
    }
    g_w1c16[fidx] = c16;
}

// ---------------- 6a. attn3 logits ----------------------------------------------
__global__ __launch_bounds__(128)
void attn3a_kernel() {
    int h = blockIdx.y;
    int t0 = blockIdx.x * 128;
    int tid = threadIdx.x;
    __shared__ float ks[128][QS];
    __shared__ float qls[MM*DH];
    #pragma unroll
    for (int i = 0; i < 16; i++) {
        int idx = i*128 + tid;
        int row = idx >> 4, c4 = idx & 15;
        int gt = t0 + row;
        float4 v = (gt < NPAD) ? *(const float4*)&g_qkv[(size_t)gt*QKVD + 512 + h*DH + c4*4]
                               : make_float4(0,0,0,0);
        *(float4*)&ks[row][c4*4] = v;
    }
    for (int idx = tid; idx < MM*DH; idx += 128) qls[idx] = g_ql[h*MM*DH + idx];
    __syncthreads();
    int t = t0 + tid;
    if (t >= NPAD) return;
    float lg[MM];
    #pragma unroll
    for (int m = 0; m < MM; m++) lg[m] = 0.f;
    #pragma unroll
    for (int d4 = 0; d4 < 16; d4++) {
        float4 k4 = *(const float4*)&ks[tid][d4*4];
        #pragma unroll
        for (int m = 0; m < MM; m++) {
            float4 q4 = *(const float4*)&qls[m*DH + d4*4];
            lg[m] += q4.x*k4.x + q4.y*k4.y + q4.z*k4.z + q4.w*k4.w;
        }
    }
    #pragma unroll
    for (int m = 0; m < MM; m++)
        g_attn3[((size_t)h*MM + m)*NPAD + t] = lg[m];
}

// ---------------- 6b. attn3 softmax normalize (1024 threads) --------------------
__global__ __launch_bounds__(1024)
void attn3b_kernel() {
    int m = blockIdx.x, h = blockIdx.y;
    int tid = threadIdx.x;
    __shared__ float buf[NPAD];
    __shared__ float red[1024];
    float* rowp = g_attn3 + ((size_t)h*MM + m)*NPAD;
    float lmax = -INFINITY;
    for (int t = tid; t < NPAD; t += 1024) { float v = rowp[t]; buf[t] = v; lmax = fmaxf(lmax, v); }
    red[tid] = lmax; __syncthreads();
    for (int o = 512; o; o >>= 1) { if (tid < o) red[tid] = fmaxf(red[tid], red[tid+o]); __syncthreads(); }
    float mx = red[0];
    __syncthreads();
    float lsum = 0.f;
    for (int t = tid; t < NPAD; t += 1024) { float e = expf(buf[t]-mx); buf[t] = e; lsum += e; }
    red[tid] = lsum; __syncthreads();
    for (int o = 512; o; o >>= 1) { if (tid < o) red[tid] += red[tid+o]; __syncthreads(); }
    float inv = 1.f / red[0];
    for (int t = tid; t < NPAD; t += 1024) rowp[t] = buf[t]*inv;
}

// ---------------- 7. av partials (chunk 257 -> covers ALL tokens) ---------------
__global__ __launch_bounds__(544)
void av_kernel() {
    int ch = blockIdx.x, h = blockIdx.y;
    int tid = threadIdx.x;
    int m = tid >> 5, lane = tid & 31;
    int start = ch * AVCHUNK;
    int end = min(start + AVCHUNK, NPAD);
    __shared__ float vs[32][QS];
    __shared__ float a3s[MM][32];
    float2 acc = make_float2(0.f, 0.f);
    int nsub = (end - start + 31) >> 5;
    for (int sub = 0; sub < nsub; sub++) {
        int base = start + sub*32;
        if (tid < 512) {
            int row = tid >> 4, c4 = tid & 15;
            int gt = base + row;
            float4 v = (gt < end) ? *(const float4*)&g_qkv[(size_t)gt*QKVD + 1024 + h*DH + c4*4]
                                  : make_float4(0,0,0,0);
            *(float4*)&vs[row][c4*4] = v;
        }
        {
            int mm = tid >> 5, tok = tid & 31;
            int gt = base + tok;
            a3s[mm][tok] = (gt < end) ? g_attn3[((size_t)h*MM + mm)*NPAD + gt] : 0.f;
        }
        __syncthreads();
        #pragma unroll
        for (int tok = 0; tok < 32; tok++) {
            float a = a3s[m][tok];
            float2 v = *(const float2*)&vs[tok][lane*2];
            acc.x += a*v.x; acc.y += a*v.y;
        }
        __syncthreads();
    }
    float* dst = g_avp + ((size_t)(ch*HEADS + h)*MM + m)*DH + lane*2;
    dst[0] = acc.x; dst[1] = acc.y;
}

// ---------------- 8b. out_heads = w1 @ av + conv -> split bf16 ---------------------
#define OTILE 96
__global__ __launch_bounds__(256)
void outh_kernel(const float* __restrict__ conv_w) {
    int h = blockIdx.y;
    int t0 = blockIdx.x * OTILE;
    int tid = threadIdx.x;
    __shared__ float vtile[OTILE+32][DH];
    __shared__ float w1s[OTILE][MM];
    __shared__ float avs[MM*DH];
    __shared__ float cws[KCONV];
    #pragma unroll
    for (int i = 0; i < (OTILE+32)*16/256; i++) {
        int idx = i*256 + tid;
        int row = idx >> 4, c4 = idx & 15;
        int gt = t0 - 16 + row;
        float4 v = (gt >= 0 && gt < NPAD) ? *(const float4*)&g_qkv[(size_t)gt*QKVD + 1024 + h*DH + c4*4]
                                          : make_float4(0,0,0,0);
        *(float4*)&vtile[row][c4*4] = v;
    }
    for (int idx = tid; idx < OTILE*MM; idx += 256) {
        int r = idx / MM, mm = idx % MM;
        int gt = t0 + r;
        w1s[r][mm] = (gt < NPAD) ? g_w1[((size_t)h*NPAD + gt)*MM + mm] : 0.f;
    }
    for (int idx = tid; idx < MM*DH; idx += 256) {
        float s = 0.f;
        #pragma unroll
        for (int c = 0; c < AVCH; c++) s += g_avp[(size_t)(c*HEADS + h)*MM*DH + idx];
        avs[idx] = s;
    }
    if (tid < KCONV) cws[tid] = conv_w[h*KCONV + tid];
    __syncthreads();
    int d = tid & 63, grp = tid >> 6;
    for (int rr = 0; rr < OTILE/4; rr++) {
        int r = grp*(OTILE/4) + rr;
        int t = t0 + r;
        if (t >= NPAD) continue;
        float acc = 0.f;
        #pragma unroll
        for (int mm = 0; mm < MM; mm++) acc += w1s[r][mm]*avs[mm*DH + d];
        #pragma unroll
        for (int k = 0; k < KCONV; k++) acc += cws[k]*vtile[r+k][d];
        size_t idx = (size_t)t*DIM + h*DH + d;
        __nv_bfloat16 bh, bm;
        split2(acc, bh, bm);
        g_oh[idx]=bh; g_om[idx]=bm;
    }
}

// ---------------- 9b. attn3 -> transposed bf16 splits + fp32 row 16 ----------------
__global__ void a3cvt_kernel() {
    int idx = blockIdx.x*256 + threadIdx.x;       // h*TPADN + s
    if (idx >= HEADS*TPADN) return;
    int h = idx / TPADN, s = idx % TPADN;
    float r16 = 0.f;
    __nv_bfloat16 vh[16], vm[16];
    if (s < NPAD) {
        #pragma unroll
        for (int k = 0; k < 16; k++)
            split2(g_attn3[((size_t)h*MM + k)*NPAD + s], vh[k], vm[k]);
        r16 = g_attn3[((size_t)h*MM + 16)*NPAD + s];
    } else {
        __nv_bfloat16 z = __float2bfloat16(0.f);
        #pragma unroll
        for (int k = 0; k < 16; k++) { vh[k]=z; vm[k]=z; }
    }
    #pragma unroll
    for (int k = 0; k < 16; k++) {
        g_fa3h[(size_t)idx*16 + k] = vh[k];
        g_fa3m[(size_t)idx*16 + k] = vm[k];
    }
    g_a3r16[idx] = r16;
}

// ---------------- 11. attn = w1 @ attn3 via HMMA (537 MB) --------------------------
#define FPITCH 48
#define FA_H 0
#define FA_M (128*FPITCH)        // 6144
#define FB_H (2*128*FPITCH)      // 12288
#define FB_M (3*128*FPITCH)      // 18432
#define FW16 (4*128*FPITCH)      // 24576
#define FA16 (FW16 + 512)        // 25088
#define TPITCH 132               // transpose buffer pitch (floats)
#define FSMEM (64*TPITCH*4 > (4*128*FPITCH + 1024) ? 64*TPITCH*4 : (4*128*FPITCH + 1024))
__global__ __launch_bounds__(256, 2)
void attn_final_mma(float* __restrict__ out) {
    __shared__ __align__(16) char sm[FSMEM];
    uint32_t sbase = s2u(sm);
    int tid = threadIdx.x, lane = tid & 31, wid = tid >> 5;
    int warp_m = wid & 3, warp_n = wid >> 2;
    int h = blockIdx.z;
    int t0 = blockIdx.y * 128, s0 = blockIdx.x * 128;

    {
        int row = tid >> 1, half = tid & 1;
        const uint4* a_h = (const uint4*)(g_fw1h + ((size_t)h*TPADN + t0)*16);
        const uint4* a_m = (const uint4*)(g_fw1m + ((size_t)h*TPADN + t0)*16);
        const uint4* b_h = (const uint4*)(g_fa3h + ((size_t)h*TPADN + s0)*16);
        const uint4* b_m = (const uint4*)(g_fa3m + ((size_t)h*TPADN + s0)*16);
        *(uint4*)(sm + FA_H + row*FPITCH + half*16) = a_h[row*2 + half];
        *(uint4*)(sm + FA_M + row*FPITCH + half*16) = a_m[row*2 + half];
        *(uint4*)(sm + FB_H + row*FPITCH + half*16) = b_h[row*2 + half];
        *(uint4*)(sm + FB_M + row*FPITCH + half*16) = b_m[row*2 + half];
        if (tid < 128) ((float*)(sm + FW16))[tid] = g_w1c16[h*TPADN + t0 + tid];
        else           ((float*)(sm + FA16))[tid-128] = g_a3r16[h*TPADN + s0 + tid - 128];
    }
    __syncthreads();

    float acc[2][8][4];
    #pragma unroll
    for (int i = 0; i < 2; i++)
        #pragma unroll
        for (int j = 0; j < 8; j++)
            #pragma unroll
            for (int v = 0; v < 4; v++) acc[i][j][v] = 0.f;

    int arow = warp_m*32 + (lane & 15);
    int akoff2 = ((lane >> 4) << 3) * 2;
    int brow = warp_n*64 + (lane & 7) + ((lane >> 4) << 3);
    int bkoff2 = (((lane >> 3) & 1) << 3) * 2;

    uint32_t afr[2][2][4];
    #pragma unroll
    for (int s = 0; s < 2; s++)
        #pragma unroll
        for (int mi = 0; mi < 2; mi++)
            ldm4(afr[s][mi], sbase + s*FA_M + (arow + mi*16)*FPITCH + akoff2);
    #pragma unroll
    for (int g = 0; g < 4; g++) {
        uint32_t bh[4], bm[4];
        ldm4(bh, sbase + FB_H + (brow + g*16)*FPITCH + bkoff2);
        ldm4(bm, sbase + FB_M + (brow + g*16)*FPITCH + bkoff2);
        #pragma unroll
        for (int mi = 0; mi < 2; mi++) {
            mma16816(acc[mi][2*g],   afr[0][mi], bh);
            mma16816(acc[mi][2*g],   afr[0][mi], bm);
            mma16816(acc[mi][2*g],   afr[1][mi], bh);
            mma16816(acc[mi][2*g+1], afr[0][mi], bh+2);
            mma16816(acc[mi][2*g+1], afr[0][mi], bm+2);
            mma16816(acc[mi][2*g+1], afr[1][mi], bh+2);
        }
    }

    {
        const float* w16f = (const float*)(sm + FW16);
        const float* a16f = (const float*)(sm + FA16);
        int g2 = lane >> 2, tg = lane & 3;
        #pragma unroll
        for (int mi = 0; mi < 2; mi++) {
            float w0 = w16f[warp_m*32 + mi*16 + g2];
            float w1v = w16f[warp_m*32 + mi*16 + g2 + 8];
            #pragma unroll
            for (int nj = 0; nj < 8; nj++) {
                int cl = warp_n*64 + nj*8 + tg*2;
                float a0 = a16f[cl], a1 = a16f[cl+1];
                acc[mi][nj][0] += w0*a0;
                acc[mi][nj][1] += w0*a1;
                acc[mi][nj][2] += w1v*a0;
                acc[mi][nj][3] += w1v*a1;
            }
        }
    }

    float* tb = (float*)sm;
    int g2 = lane >> 2, tg = lane & 3;
    float* obase = out + (size_t)h*ATTN_PER_HEAD;
    #pragma unroll
    for (int mi = 0; mi < 2; mi++) {
        __syncthreads();
        int lr = warp_m*16 + g2;
        #pragma unroll
        for (int nj = 0; nj < 8; nj++) {
            int cl = warp_n*64 + nj*8 + tg*2;
            tb[lr*TPITCH + cl]         = acc[mi][nj][0];
            tb[lr*TPITCH + cl + 1]     = acc[mi][nj][1];
            tb[(lr+8)*TPITCH + cl]     = acc[mi][nj][2];
            tb[(lr+8)*TPITCH + cl + 1] = acc[mi][nj][3];
        }
        __syncthreads();
        #pragma unroll 8
        for (int i = 0; i < 32; i++) {
            int idx = i*256 + tid;
            int r = idx >> 7, c = idx & 127;
            int gr = t0 + (r >> 4)*32 + mi*16 + (r & 15);
            int gc = s0 + c;
            if (gr < NPAD && gc < NPAD)
                __stcs(obase + (size_t)gr*NPAD + gc, tb[r*TPITCH + c]);
        }
    }
}

// ---------------- launch -------------------------------------------------------------
extern "C" void kernel_launch(void* const* d_in, const int* in_sizes, int n_in,
                              void* d_out, int out_size) {
    const float* x      = (const float*)d_in[0];
    const float* norm_w = (const float*)d_in[1];
    const float* norm_b = (const float*)d_in[2];
    const float* w_qkv  = (const float*)d_in[3];
    const float* w_out  = (const float*)d_in[4];
    const float* b_out  = (const float*)d_in[5];
    const float* conv_w = (const float*)d_in[6];
    float* out = (float*)d_out;

    float* p_qkv;
    cudaGetSymbolAddress((void**)&p_qkv, g_qkv);
    __nv_bfloat16 *p_ah, *p_am, *p_oh, *p_om;
    __nv_bfloat16 *p_wqh, *p_wqm, *p_woh, *p_wom;
    cudaGetSymbolAddress((void**)&p_ah, g_ah);  cudaGetSymbolAddress((void**)&p_am, g_am);
    cudaGetSymbolAddress((void**)&p_oh, g_oh);  cudaGetSymbolAddress((void**)&p_om, g_om);
    cudaGetSymbolAddress((void**)&p_wqh, g_wqh); cudaGetSymbolAddress((void**)&p_wqm, g_wqm);
    cudaGetSymbolAddress((void**)&p_woh, g_woh); cudaGetSymbolAddress((void**)&p_wom, g_wom);

    cudaFuncSetAttribute(gemm_mma, cudaFuncAttributeMaxDynamicSharedMemorySize, GSMEM);

    ln_kernel<<<NPAD, 256>>>(x, norm_w, norm_b);
    wcvt_kernel<<<(NWQ + NWO + 255)/256, 256>>>(w_qkv, w_out);
    gemm_mma<<<dim3(QKVD/128, (NPAD+127)/128), 256, GSMEM>>>(
        p_ah, p_am, p_wqh, p_wqm, p_qkv, NPAD, QKVD, DIM, 0, nullptr, nullptr);
    landmark_kernel<<<dim3(MM, 2), 512>>>();
    pinv_kernel<<<HEADS, MM*MM>>>();
    attn1w1_kernel<<<dim3((NPAD+127)/128, HEADS), 128>>>();   // also emits w1 splits
    attn3a_kernel<<<dim3((NPAD+127)/128, HEADS), 128>>>();
    attn3b_kernel<<<dim3(MM, HEADS), 1024>>>();
    av_kernel<<<dim3(AVCH, HEADS), 544>>>();
    outh_kernel<<<dim3((NPAD+OTILE-1)/OTILE, HEADS), 256>>>(conv_w);
    gemm_mma<<<dim3(DIM/128, NTOK/128), 256, GSMEM>>>(
        p_oh + DIM, p_om + DIM, p_woh, p_wom,
        out, NTOK, DIM, DIM, 1, b_out, x);
    a3cvt_kernel<<<(HEADS*TPADN + 255)/256, 256>>>();
    attn_final_mma<<<dim3(TPADN/128, TPADN/128, HEADS), 256>>>(out + OUT1_SIZE);
}

// round 15
// speedup vs baseline: 1.0030x; 1.0030x over previous
#include <cuda_runtime.h>
#include <cuda_bf16.h>
#include <math.h>
#include <stdint.h>

#define NTOK 4096
#define NPAD 4097
#define TPADN 4224          // 33*128, padded token count for mma tiles
#define DIM 512
#define HEADS 8
#define DH 64
#define MM 17
#define LBLK 241
#define QKVD 1536
#define KCONV 33
#define OUT1_SIZE (NTOK*DIM)
#define ATTN_PER_HEAD ((size_t)NPAD*NPAD)
#define AVCH 16
#define AVCHUNK ((NPAD + AVCH - 1)/AVCH)   // 257
#define LMCH 8
#define LMROWS ((LBLK + LMCH - 1)/LMCH)    // 31

// ---------------- scratch ---------------------------------------------------
__device__ float g_qkv[NPAD*QKVD];
__device__ float g_ql[HEADS*MM*DH];
__device__ float g_kl[HEADS*MM*DH];
__device__ float g_attn3[HEADS*MM*NPAD];
__device__ float g_inv[HEADS*MM*MM];
__device__ float g_avp[AVCH*HEADS*MM*DH];
__device__ float g_w1[HEADS*NPAD*MM];
__device__ float g_lmp[2*MM*LMCH*DIM];     // landmark partials
// bf16 2-way splits (hi, mid)
__device__ __nv_bfloat16 g_ah[NPAD*DIM], g_am[NPAD*DIM];
__device__ __nv_bfloat16 g_oh[NPAD*DIM], g_om[NPAD*DIM];
__device__ __nv_bfloat16 g_wqh[QKVD*DIM], g_wqm[QKVD*DIM];
__device__ __nv_bfloat16 g_woh[DIM*DIM], g_wom[DIM*DIM];
// attn-final mma operands: k 0..15 as bf16 splits, k=16 as fp32
__device__ __nv_bfloat16 g_fw1h[HEADS*TPADN*16], g_fw1m[HEADS*TPADN*16];
__device__ __nv_bfloat16 g_fa3h[HEADS*TPADN*16], g_fa3m[HEADS*TPADN*16];
__device__ float g_w1c16[HEADS*TPADN];
__device__ float g_a3r16[HEADS*TPADN];

__device__ __forceinline__ uint32_t s2u(const void* p) {
    return (uint32_t)__cvta_generic_to_shared(p);
}
__device__ __forceinline__ void split2(float x, __nv_bfloat16& h, __nv_bfloat16& m) {
    h = __float2bfloat16(x);
    float r1 = x - __bfloat162float(h);
    m = __float2bfloat16(r1);
}

// ---------------- 1. LayerNorm -> split bf16 ---------------------------------
__global__ void ln_kernel(const float* __restrict__ x,
                          const float* __restrict__ w,
                          const float* __restrict__ b) {
    int r = blockIdx.x;
    int tid = threadIdx.x;
    if (r == 0) {
        __nv_bfloat16 z = __float2bfloat16(0.f);
        for (int c = tid; c < DIM; c += 256) { g_ah[c]=z; g_am[c]=z; }
        return;
    }
    const float* row = x + (size_t)(r-1)*DIM;
    __shared__ float red[256];
    float s = 0.f;
    for (int c = tid; c < DIM; c += 256) s += row[c];
    red[tid] = s; __syncthreads();
    for (int o = 128; o; o >>= 1) { if (tid < o) red[tid] += red[tid+o]; __syncthreads(); }
    float mu = red[0] * (1.0f/DIM);
    __syncthreads();
    float v = 0.f;
    for (int c = tid; c < DIM; c += 256) { float d = row[c]-mu; v += d*d; }
    red[tid] = v; __syncthreads();
    for (int o = 128; o; o >>= 1) { if (tid < o) red[tid] += red[tid+o]; __syncthreads(); }
    float rs = rsqrtf(red[0]*(1.0f/DIM) + 1e-5f);
    for (int c = tid; c < DIM; c += 256) {
        float val = (row[c]-mu)*rs*w[c] + b[c];
        __nv_bfloat16 h, m;
        split2(val, h, m);
        size_t idx = (size_t)r*DIM + c;
        g_ah[idx]=h; g_am[idx]=m;
    }
}

// ---------------- weight split (both matrices, one launch) --------------------
#define NWQ (QKVD*DIM)
#define NWO (DIM*DIM)
__global__ void wcvt_kernel(const float* __restrict__ wq, const float* __restrict__ wo) {
    int i = blockIdx.x*256 + threadIdx.x;
    if (i < NWQ) {
        split2(wq[i], g_wqh[i], g_wqm[i]);
    } else if (i < NWQ + NWO) {
        int j = i - NWQ;
        split2(wo[j], g_woh[j], g_wom[j]);
    }
}

// ---------------- mma.sync bf16 GEMM: C = A(MxK) @ B^T ------------------------
#define TPAD 40
#define TILE_B (128*TPAD*2)      // 10240 bytes per tile
#define STAGE_B (4*TILE_B)       // 40960
#define GSMEM (2*STAGE_B)        // 81920 (2 stages -> 2 CTAs/SM)

__device__ __forceinline__ void cp16(uint32_t daddr, const void* g, int sz) {
    asm volatile("cp.async.ca.shared.global [%0], [%1], 16, %2;"
                 :: "r"(daddr), "l"(g), "r"(sz));
}
__device__ __forceinline__ void ldm4(uint32_t* r, uint32_t addr) {
    asm volatile("ldmatrix.sync.aligned.m8n8.x4.shared.b16 {%0,%1,%2,%3}, [%4];"
                 : "=r"(r[0]), "=r"(r[1]), "=r"(r[2]), "=r"(r[3]) : "r"(addr));
}
__device__ __forceinline__ void mma16816(float* c, const uint32_t* a, const uint32_t* b) {
    asm volatile("mma.sync.aligned.m16n8k16.row.col.f32.bf16.bf16.f32 "
                 "{%0,%1,%2,%3}, {%4,%5,%6,%7}, {%8,%9}, {%0,%1,%2,%3};"
                 : "+f"(c[0]), "+f"(c[1]), "+f"(c[2]), "+f"(c[3])
                 : "r"(a[0]), "r"(a[1]), "r"(a[2]), "r"(a[3]), "r"(b[0]), "r"(b[1]));
}

__global__ __launch_bounds__(256, 2)
void gemm_mma(const __nv_bfloat16* __restrict__ a0, const __nv_bfloat16* __restrict__ a1,
              const __nv_bfloat16* __restrict__ b0, const __nv_bfloat16* __restrict__ b1,
              float* __restrict__ C, int M, int N, int K, int mode,
              const float* __restrict__ bias, const float* __restrict__ resid) {
    extern __shared__ char smem[];
    uint32_t sbase = s2u(smem);
    int tid = threadIdx.x, lane = tid & 31, wid = tid >> 5;
    int warp_m = wid & 3, warp_n = wid >> 2;
    int m0 = blockIdx.y * 128, n0 = blockIdx.x * 128;
    const __nv_bfloat16* asrc[2] = {a0, a1};
    const __nv_bfloat16* bsrc[2] = {b0, b1};

    int ldrow = tid >> 2, ldc4 = tid & 3;
    float acc[2][8][4];
    #pragma unroll
    for (int i = 0; i < 2; i++)
        #pragma unroll
        for (int j = 0; j < 8; j++)
            #pragma unroll
            for (int v = 0; v < 4; v++) acc[i][j][v] = 0.f;

    int nchunks = K / 32;

    auto stage = [&](int chunk, int buf) {
        int k0 = chunk * 32;
        uint32_t stb = sbase + buf*STAGE_B;
        #pragma unroll
        for (int s = 0; s < 4; s++) {
            const __nv_bfloat16* src = (s < 2) ? asrc[s] : bsrc[s-2];
            int base = (s < 2) ? m0 : n0;
            uint32_t tb = stb + s*TILE_B;
            #pragma unroll
            for (int i = 0; i < 2; i++) {
                int row = ldrow + i*64;
                int gr = base + row;
                int ok = (s >= 2) || (gr < M);
                int grc = ok ? gr : 0;
                cp16(tb + row*80 + ldc4*16, src + (size_t)grc*K + k0 + ldc4*8, ok ? 16 : 0);
            }
        }
        asm volatile("cp.async.commit_group;");
    };

    stage(0, 0);

    int arow = warp_m*32 + (lane & 15);
    int akoff = ((lane >> 4) << 3);
    int brow = warp_n*64 + (lane & 7) + ((lane >> 4) << 3);
    int bkoff = ((lane >> 3) & 1) << 3;

    for (int c = 0; c < nchunks; c++) {
        if (c + 1 < nchunks) {
            stage(c + 1, (c + 1) & 1);
            asm volatile("cp.async.wait_group 1;");
        } else {
            asm volatile("cp.async.wait_group 0;");
        }
        __syncthreads();
        uint32_t stb = sbase + (c & 1)*STAGE_B;
        #pragma unroll
        for (int k16 = 0; k16 < 2; k16++) {
            uint32_t afr[2][2][4];
            #pragma unroll
            for (int s = 0; s < 2; s++)
                #pragma unroll
                for (int mi = 0; mi < 2; mi++)
                    ldm4(afr[s][mi], stb + s*TILE_B + (arow + mi*16)*80 + (akoff + k16*16)*2);
            #pragma unroll
            for (int g = 0; g < 4; g++) {
                uint32_t bh[4], bm[4];
                ldm4(bh, stb + 2*TILE_B + (brow + g*16)*80 + (bkoff + k16*16)*2);
                ldm4(bm, stb + 3*TILE_B + (brow + g*16)*80 + (bkoff + k16*16)*2);
                #pragma unroll
                for (int mi = 0; mi < 2; mi++) {
                    mma16816(acc[mi][2*g],   afr[0][mi], bh);
                    mma16816(acc[mi][2*g],   afr[0][mi], bm);
                    mma16816(acc[mi][2*g],   afr[1][mi], bh);
                    mma16816(acc[mi][2*g+1], afr[0][mi], bh+2);
                    mma16816(acc[mi][2*g+1], afr[0][mi], bm+2);
                    mma16816(acc[mi][2*g+1], afr[1][mi], bh+2);
                }
            }
        }
        __syncthreads();
    }

    // ---- epilogue
    int g = lane >> 2, tg = lane & 3;
    #pragma unroll
    for (int mi = 0; mi < 2; mi++) {
        #pragma unroll
        for (int nj = 0; nj < 8; nj++) {
            int col = n0 + warp_n*64 + nj*8 + tg*2;
            int r0 = m0 + warp_m*32 + mi*16 + g;
            int r1 = r0 + 8;
            float v0 = acc[mi][nj][0], v1 = acc[mi][nj][1];
            float v2 = acc[mi][nj][2], v3 = acc[mi][nj][3];
            if (mode == 0) {
                if (col < 512) { v0 *= 0.125f; v1 *= 0.125f; v2 *= 0.125f; v3 *= 0.125f; }
                if (r0 < M) { C[(size_t)r0*N + col] = v0; C[(size_t)r0*N + col + 1] = v1; }
                if (r1 < M) { C[(size_t)r1*N + col] = v2; C[(size_t)r1*N + col + 1] = v3; }
            } else {
                float bb0 = bias[col], bb1 = bias[col+1];
                if (r0 < M) {
                    size_t o = (size_t)r0*N + col;
                    C[o]   = v0 + bb0 + resid[o];
                    C[o+1] = v1 + bb1 + resid[o+1];
                }
                if (r1 < M) {
                    size_t o = (size_t)r1*N + col;
                    C[o]   = v2 + bb0 + resid[o];
                    C[o+1] = v3 + bb1 + resid[o+1];
                }
            }
        }
    }
}

// ---------------- 3a. landmark partials (8 chunks per (m,which)) ----------------
__global__ void landmark_kernel() {
    int m = blockIdx.x, which = blockIdx.y, ch = blockIdx.z;
    int c = threadIdx.x;
    int base = which ? 512 : 0;
    int r0 = ch * LMROWS;
    int r1 = min(r0 + LMROWS, LBLK);
    const float* p = g_qkv + (size_t)(m*LBLK + r0)*QKVD + base + c;
    float s = 0.f;
    for (int i = r0; i < r1; i++) { s += *p; p += QKVD; }
    g_lmp[(((size_t)which*MM + m)*LMCH + ch)*DIM + c] = s;
}

// ---------------- 3b. landmark reduce -------------------------------------------
__global__ void landmark2_kernel() {
    int m = blockIdx.x, which = blockIdx.y;
    int c = threadIdx.x;
    const float* p = g_lmp + ((size_t)which*MM + m)*LMCH*DIM + c;
    float s = 0.f;
    #pragma unroll
    for (int ch = 0; ch < LMCH; ch++) s += p[ch*DIM];
    float v = s * (1.0f/LBLK);
    int h = c >> 6, d = c & 63;
    if (which) g_kl[(h*MM+m)*DH + d] = v; else g_ql[(h*MM+m)*DH + d] = v;
}

// ---------------- 5. attn2 softmax + pinv --------------------------------------
__global__ void pinv_kernel() {
    int h = blockIdx.x;
    int tid = threadIdx.x;          // 289
    int i = tid / MM, j = tid % MM;
    __shared__ float a[MM][MM], zz[2][MM][MM], az[MM][MM], t2[MM][MM], t3[MM][MM];
    __shared__ float sc;
    {
        const float* ql = g_ql + (h*MM + i)*DH;
        const float* kl = g_kl + (h*MM + j)*DH;
        float s = 0.f;
        #pragma unroll
        for (int d = 0; d < DH; d++) s += ql[d]*kl[d];
        a[i][j] = s;
    }
    __syncthreads();
    if (tid < MM) {
        float mx = -INFINITY;
        for (int c = 0; c < MM; c++) mx = fmaxf(mx, a[tid][c]);
        float s = 0.f;
        for (int c = 0; c < MM; c++) { float e = expf(a[tid][c]-mx); a[tid][c] = e; s += e; }
        float inv = 1.f/s;
        for (int c = 0; c < MM; c++) a[tid][c] *= inv;
    }
    __syncthreads();
    if (tid == 0) {
        float col = 0.f, row = 0.f;
        for (int r = 0; r < MM; r++) { float s = 0.f; for (int c = 0; c < MM; c++) s += fabsf(a[r][c]); col = fmaxf(col, s); }
        for (int c = 0; c < MM; c++) { float s = 0.f; for (int r = 0; r < MM; r++) s += fabsf(a[r][c]); row = fmaxf(row, s); }
        sc = 1.f/(col*row);
    }
    __syncthreads();
    int zc = 0;
    zz[0][i][j] = a[j][i] * sc;
    __syncthreads();
    for (int it = 0; it < 6; it++) {
        float s = 0.f;
        for (int k = 0; k < MM; k++) s += a[i][k]*zz[zc][k][j];
        az[i][j] = s; __syncthreads();
        s = 0.f;
        for (int k = 0; k < MM; k++) s += az[i][k]*((k==j ? 7.f : 0.f) - az[k][j]);
        t2[i][j] = (i==j ? 15.f : 0.f) - s; __syncthreads();
        s = 0.f;
        for (int k = 0; k < MM; k++) s += az[i][k]*t2[k][j];
        t3[i][j] = (i==j ? 13.f : 0.f) - s; __syncthreads();
        s = 0.f;
        for (int k = 0; k < MM; k++) s += zz[zc][i][k]*t3[k][j];
        zz[1-zc][i][j] = 0.25f*s; zc ^= 1; __syncthreads();
    }
    g_inv[(h*MM + i)*MM + j] = zz[zc][i][j];
}

// ---------------- 4+8a fused: w1 = softmax(q @ kl^T) @ inv ----------------------
#define QS 68
__global__ __launch_bounds__(128)
void attn1w1_kernel() {
    int h = blockIdx.y;
    int t0 = blockIdx.x * 128;
    int tid = threadIdx.x;
    __shared__ float qs[128][QS];
    __shared__ float kls[MM*DH];
    __shared__ float invs[MM*MM];
    #pragma unroll
    for (int i = 0; i < 16; i++) {
        int idx = i*128 + tid;
        int row = idx >> 4, c4 = idx & 15;
        int gt = t0 + row;
        float4 v = (gt < NPAD) ? *(const float4*)&g_qkv[(size_t)gt*QKVD + h*DH + c4*4]
                               : make_float4(0,0,0,0);
        *(float4*)&qs[row][c4*4] = v;
    }
    for (int idx = tid; idx < MM*DH; idx += 128) kls[idx] = g_kl[h*MM*DH + idx];
    for (int idx = tid; idx < MM*MM; idx += 128) invs[idx] = g_inv[h*MM*MM + idx];
    __syncthreads();
    int t = t0 + tid;
    size_t fidx = (size_t)h*TPADN + t;
    if (t >= NPAD) {
        uint4 z = make_uint4(0,0,0,0);
        *(uint4*)(g_fw1h + fidx*16)     = z;
        *(uint4*)(g_fw1h + fidx*16 + 8) = z;
        *(uint4*)(g_fw1m + fidx*16)     = z;
        *(uint4*)(g_fw1m + fidx*16 + 8) = z;
        g_w1c16[fidx] = 0.f;
        return;
    }
    float lg[MM];
    #pragma unroll
    for (int m = 0; m < MM; m++) lg[m] = 0.f;
    #pragma unroll
    for (int d4 = 0; d4 < 16; d4++) {
        float4 q4 = *(const float4*)&qs[tid][d4*4];
        #pragma unroll
        for (int m = 0; m < MM; m++) {
            float4 k4 = *(const float4*)&kls[m*DH + d4*4];
            lg[m] += q4.x*k4.x + q4.y*k4.y + q4.z*k4.z + q4.w*k4.w;
        }
    }
    float mx = lg[0];
    #pragma unroll
    for (int m = 1; m < MM; m++) mx = fmaxf(mx, lg[m]);
    float sum = 0.f;
    #pragma unroll
    for (int m = 0; m < MM; m++) { lg[m] = expf(lg[m]-mx); sum += lg[m]; }
    float inv = 1.f/sum;
    #pragma unroll
    for (int m = 0; m < MM; m++) lg[m] *= inv;
    float* wout = g_w1 + ((size_t)h*NPAD + t)*MM;
    __nv_bfloat16 sh[16], smd[16];
    float c16 = 0.f;
    #pragma unroll
    for (int j = 0; j < MM; j++) {
        float s = 0.f;
        #pragma unroll
        for (int k = 0; k < MM; k++) s += lg[k]*invs[k*MM + j];
        wout[j] = s;
        if (j < 16) split2(s, sh[j], smd[j]);
        else c16 = s;
    }
    #pragma unroll
    for (int j = 0; j < 16; j++) {
        g_fw1h[fidx*16 + j] = sh[j];
        g_fw1m[fidx*16 + j] = smd[j];
    }
    g_w1c16[fidx] = c16;
}

// ---------------- 6a. attn3 logits ----------------------------------------------
__global__ __launch_bounds__(128)
void attn3a_kernel() {
    int h = blockIdx.y;
    int t0 = blockIdx.x * 128;
    int tid = threadIdx.x;
    __shared__ float ks[128][QS];
    __shared__ float qls[MM*DH];
    #pragma unroll
    for (int i = 0; i < 16; i++) {
        int idx = i*128 + tid;
        int row = idx >> 4, c4 = idx & 15;
        int gt = t0 + row;
        float4 v = (gt < NPAD) ? *(const float4*)&g_qkv[(size_t)gt*QKVD + 512 + h*DH + c4*4]
                               : make_float4(0,0,0,0);
        *(float4*)&ks[row][c4*4] = v;
    }
    for (int idx = tid; idx < MM*DH; idx += 128) qls[idx] = g_ql[h*MM*DH + idx];
    __syncthreads();
    int t = t0 + tid;
    if (t >= NPAD) return;
    float lg[MM];
    #pragma unroll
    for (int m = 0; m < MM; m++) lg[m] = 0.f;
    #pragma unroll
    for (int d4 = 0; d4 < 16; d4++) {
        float4 k4 = *(const float4*)&ks[tid][d4*4];
        #pragma unroll
        for (int m = 0; m < MM; m++) {
            float4 q4 = *(const float4*)&qls[m*DH + d4*4];
            lg[m] += q4.x*k4.x + q4.y*k4.y + q4.z*k4.z + q4.w*k4.w;
        }
    }
    #pragma unroll
    for (int m = 0; m < MM; m++)
        g_attn3[((size_t)h*MM + m)*NPAD + t] = lg[m];
}

// ---------------- 6b. attn3 softmax normalize (1024 threads) --------------------
__global__ __launch_bounds__(1024)
void attn3b_kernel() {
    int m = blockIdx.x, h = blockIdx.y;
    int tid = threadIdx.x;
    __shared__ float buf[NPAD];
    __shared__ float red[1024];
    float* rowp = g_attn3 + ((size_t)h*MM + m)*NPAD;
    float lmax = -INFINITY;
    for (int t = tid; t < NPAD; t += 1024) { float v = rowp[t]; buf[t] = v; lmax = fmaxf(lmax, v); }
    red[tid] = lmax; __syncthreads();
    for (int o = 512; o; o >>= 1) { if (tid < o) red[tid] = fmaxf(red[tid], red[tid+o]); __syncthreads(); }
    float mx = red[0];
    __syncthreads();
    float lsum = 0.f;
    for (int t = tid; t < NPAD; t += 1024) { float e = expf(buf[t]-mx); buf[t] = e; lsum += e; }
    red[tid] = lsum; __syncthreads();
    for (int o = 512; o; o >>= 1) { if (tid < o) red[tid] += red[tid+o]; __syncthreads(); }
    float inv = 1.f / red[0];
    for (int t = tid; t < NPAD; t += 1024) rowp[t] = buf[t]*inv;
}

// ---------------- 7. av partials (chunk 257 -> covers ALL tokens) ---------------
__global__ __launch_bounds__(544)
void av_kernel() {
    int ch = blockIdx.x, h = blockIdx.y;
    int tid = threadIdx.x;
    int m = tid >> 5, lane = tid & 31;
    int start = ch * AVCHUNK;
    int end = min(start + AVCHUNK, NPAD);
    __shared__ float vs[32][QS];
    __shared__ float a3s[MM][32];
    float2 acc = make_float2(0.f, 0.f);
    int nsub = (end - start + 31) >> 5;
    for (int sub = 0; sub < nsub; sub++) {
        int base = start + sub*32;
        if (tid < 512) {
            int row = tid >> 4, c4 = tid & 15;
            int gt = base + row;
            float4 v = (gt < end) ? *(const float4*)&g_qkv[(size_t)gt*QKVD + 1024 + h*DH + c4*4]
                                  : make_float4(0,0,0,0);
            *(float4*)&vs[row][c4*4] = v;
        }
        {
            int mm = tid >> 5, tok = tid & 31;
            int gt = base + tok;
            a3s[mm][tok] = (gt < end) ? g_attn3[((size_t)h*MM + mm)*NPAD + gt] : 0.f;
        }
        __syncthreads();
        #pragma unroll
        for (int tok = 0; tok < 32; tok++) {
            float a = a3s[m][tok];
            float2 v = *(const float2*)&vs[tok][lane*2];
            acc.x += a*v.x; acc.y += a*v.y;
        }
        __syncthreads();
    }
    float* dst = g_avp + ((size_t)(ch*HEADS + h)*MM + m)*DH + lane*2;
    dst[0] = acc.x; dst[1] = acc.y;
}

// ---------------- 8b. out_heads = w1 @ av + conv -> split bf16 ---------------------
#define OTILE 96
__global__ __launch_bounds__(256)
void outh_kernel(const float* __restrict__ conv_w) {
    int h = blockIdx.y;
    int t0 = blockIdx.x * OTILE;
    int tid = threadIdx.x;
    __shared__ float vtile[OTILE+32][DH];
    __shared__ float w1s[OTILE][MM];
    __shared__ float avs[MM*DH];
    __shared__ float cws[KCONV];
    #pragma unroll
    for (int i = 0; i < (OTILE+32)*16/256; i++) {
        int idx = i*256 + tid;
        int row = idx >> 4, c4 = idx & 15;
        int gt = t0 - 16 + row;
        float4 v = (gt >= 0 && gt < NPAD) ? *(const float4*)&g_qkv[(size_t)gt*QKVD + 1024 + h*DH + c4*4]
                                          : make_float4(0,0,0,0);
        *(float4*)&vtile[row][c4*4] = v;
    }
    for (int idx = tid; idx < OTILE*MM; idx += 256) {
        int r = idx / MM, mm = idx % MM;
        int gt = t0 + r;
        w1s[r][mm] = (gt < NPAD) ? g_w1[((size_t)h*NPAD + gt)*MM + mm] : 0.f;
    }
    for (int idx = tid; idx < MM*DH; idx += 256) {
        float s = 0.f;
        #pragma unroll
        for (int c = 0; c < AVCH; c++) s += g_avp[(size_t)(c*HEADS + h)*MM*DH + idx];
        avs[idx] = s;
    }
    if (tid < KCONV) cws[tid] = conv_w[h*KCONV + tid];
    __syncthreads();
    int d = tid & 63, grp = tid >> 6;
    for (int rr = 0; rr < OTILE/4; rr++) {
        int r = grp*(OTILE/4) + rr;
        int t = t0 + r;
        if (t >= NPAD) continue;
        float acc = 0.f;
        #pragma unroll
        for (int mm = 0; mm < MM; mm++) acc += w1s[r][mm]*avs[mm*DH + d];
        #pragma unroll
        for (int k = 0; k < KCONV; k++) acc += cws[k]*vtile[r+k][d];
        size_t idx = (size_t)t*DIM + h*DH + d;
        __nv_bfloat16 bh, bm;
        split2(acc, bh, bm);
        g_oh[idx]=bh; g_om[idx]=bm;
    }
}

// ---------------- 9b. attn3 -> transposed bf16 splits + fp32 row 16 ----------------
__global__ void a3cvt_kernel() {
    int idx = blockIdx.x*256 + threadIdx.x;       // h*TPADN + s
    if (idx >= HEADS*TPADN) return;
    int h = idx / TPADN, s = idx % TPADN;
    float r16 = 0.f;
    __nv_bfloat16 vh[16], vm[16];
    if (s < NPAD) {
        #pragma unroll
        for (int k = 0; k < 16; k++)
            split2(g_attn3[((size_t)h*MM + k)*NPAD + s], vh[k], vm[k]);
        r16 = g_attn3[((size_t)h*MM + 16)*NPAD + s];
    } else {
        __nv_bfloat16 z = __float2bfloat16(0.f);
        #pragma unroll
        for (int k = 0; k < 16; k++) { vh[k]=z; vm[k]=z; }
    }
    #pragma unroll
    for (int k = 0; k < 16; k++) {
        g_fa3h[(size_t)idx*16 + k] = vh[k];
        g_fa3m[(size_t)idx*16 + k] = vm[k];
    }
    g_a3r16[idx] = r16;
}

// ---------------- 11. attn = w1 @ attn3 via HMMA (537 MB) --------------------------
#define FPITCH 48
#define FA_H 0
#define FA_M (128*FPITCH)        // 6144
#define FB_H (2*128*FPITCH)      // 12288
#define FB_M (3*128*FPITCH)      // 18432
#define FW16 (4*128*FPITCH)      // 24576
#define FA16 (FW16 + 512)        // 25088
#define TPITCH 132               // transpose buffer pitch (floats)
#define FSMEM (64*TPITCH*4 > (4*128*FPITCH + 1024) ? 64*TPITCH*4 : (4*128*FPITCH + 1024))
__global__ __launch_bounds__(256, 2)
void attn_final_mma(float* __restrict__ out) {
    __shared__ __align__(16) char sm[FSMEM];
    uint32_t sbase = s2u(sm);
    int tid = threadIdx.x, lane = tid & 31, wid = tid >> 5;
    int warp_m = wid & 3, warp_n = wid >> 2;
    int h = blockIdx.z;
    int t0 = blockIdx.y * 128, s0 = blockIdx.x * 128;

    {
        int row = tid >> 1, half = tid & 1;
        const uint4* a_h = (const uint4*)(g_fw1h + ((size_t)h*TPADN + t0)*16);
        const uint4* a_m = (const uint4*)(g_fw1m + ((size_t)h*TPADN + t0)*16);
        const uint4* b_h = (const uint4*)(g_fa3h + ((size_t)h*TPADN + s0)*16);
        const uint4* b_m = (const uint4*)(g_fa3m + ((size_t)h*TPADN + s0)*16);
        *(uint4*)(sm + FA_H + row*FPITCH + half*16) = a_h[row*2 + half];
        *(uint4*)(sm + FA_M + row*FPITCH + half*16) = a_m[row*2 + half];
        *(uint4*)(sm + FB_H + row*FPITCH + half*16) = b_h[row*2 + half];
        *(uint4*)(sm + FB_M + row*FPITCH + half*16) = b_m[row*2 + half];
        if (tid < 128) ((float*)(sm + FW16))[tid] = g_w1c16[h*TPADN + t0 + tid];
        else           ((float*)(sm + FA16))[tid-128] = g_a3r16[h*TPADN + s0 + tid - 128];
    }
    __syncthreads();

    float acc[2][8][4];
    #pragma unroll
    for (int i = 0; i < 2; i++)
        #pragma unroll
        for (int j = 0; j < 8; j++)
            #pragma unroll
            for (int v = 0; v < 4; v++) acc[i][j][v] = 0.f;

    int arow = warp_m*32 + (lane & 15);
    int akoff2 = ((lane >> 4) << 3) * 2;
    int brow = warp_n*64 + (lane & 7) + ((lane >> 4) << 3);
    int bkoff2 = (((lane >> 3) & 1) << 3) * 2;

    uint32_t afr[2][2][4];
    #pragma unroll
    for (int s = 0; s < 2; s++)
        #pragma unroll
        for (int mi = 0; mi < 2; mi++)
            ldm4(afr[s][mi], sbase + s*FA_M + (arow + mi*16)*FPITCH + akoff2);
    #pragma unroll
    for (int g = 0; g < 4; g++) {
        uint32_t bh[4], bm[4];
        ldm4(bh, sbase + FB_H + (brow + g*16)*FPITCH + bkoff2);
        ldm4(bm, sbase + FB_M + (brow + g*16)*FPITCH + bkoff2);
        #pragma unroll
        for (int mi = 0; mi < 2; mi++) {
            mma16816(acc[mi][2*g],   afr[0][mi], bh);
            mma16816(acc[mi][2*g],   afr[0][mi], bm);
            mma16816(acc[mi][2*g],   afr[1][mi], bh);
            mma16816(acc[mi][2*g+1], afr[0][mi], bh+2);
            mma16816(acc[mi][2*g+1], afr[0][mi], bm+2);
            mma16816(acc[mi][2*g+1], afr[1][mi], bh+2);
        }
    }

    {
        const float* w16f = (const float*)(sm + FW16);
        const float* a16f = (const float*)(sm + FA16);
        int g2 = lane >> 2, tg = lane & 3;
        #pragma unroll
        for (int mi = 0; mi < 2; mi++) {
            float w0 = w16f[warp_m*32 + mi*16 + g2];
            float w1v = w16f[warp_m*32 + mi*16 + g2 + 8];
            #pragma unroll
            for (int nj = 0; nj < 8; nj++) {
                int cl = warp_n*64 + nj*8 + tg*2;
                float a0 = a16f[cl], a1 = a16f[cl+1];
                acc[mi][nj][0] += w0*a0;
                acc[mi][nj][1] += w0*a1;
                acc[mi][nj][2] += w1v*a0;
                acc[mi][nj][3] += w1v*a1;
            }
        }
    }

    float* tb = (float*)sm;
    int g2 = lane >> 2, tg = lane & 3;
    float* obase = out + (size_t)h*ATTN_PER_HEAD;
    #pragma unroll
    for (int mi = 0; mi < 2; mi++) {
        __syncthreads();
        int lr = warp_m*16 + g2;
        #pragma unroll
        for (int nj = 0; nj < 8; nj++) {
            int cl = warp_n*64 + nj*8 + tg*2;
            tb[lr*TPITCH + cl]         = acc[mi][nj][0];
            tb[lr*TPITCH + cl + 1]     = acc[mi][nj][1];
            tb[(lr+8)*TPITCH + cl]     = acc[mi][nj][2];
            tb[(lr+8)*TPITCH + cl + 1] = acc[mi][nj][3];
        }
        __syncthreads();
        #pragma unroll 8
        for (int i = 0; i < 32; i++) {
            int idx = i*256 + tid;
            int r = idx >> 7, c = idx & 127;
            int gr = t0 + (r >> 4)*32 + mi*16 + (r & 15);
            int gc = s0 + c;
            if (gr < NPAD && gc < NPAD)
                __stcs(obase + (size_t)gr*NPAD + gc, tb[r*TPITCH + c]);
        }
    }
}

// ---------------- launch -------------------------------------------------------------
extern "C" void kernel_launch(void* const* d_in, const int* in_sizes, int n_in,
                              void* d_out, int out_size) {
    const float* x      = (const float*)d_in[0];
    const float* norm_w = (const float*)d_in[1];
    const float* norm_b = (const float*)d_in[2];
    const float* w_qkv  = (const float*)d_in[3];
    const float* w_out  = (const float*)d_in[4];
    const float* b_out  = (const float*)d_in[5];
    const float* conv_w = (const float*)d_in[6];
    float* out = (float*)d_out;

    float* p_qkv;
    cudaGetSymbolAddress((void**)&p_qkv, g_qkv);
    __nv_bfloat16 *p_ah, *p_am, *p_oh, *p_om;
    __nv_bfloat16 *p_wqh, *p_wqm, *p_woh, *p_wom;
    cudaGetSymbolAddress((void**)&p_ah, g_ah);  cudaGetSymbolAddress((void**)&p_am, g_am);
    cudaGetSymbolAddress((void**)&p_oh, g_oh);  cudaGetSymbolAddress((void**)&p_om, g_om);
    cudaGetSymbolAddress((void**)&p_wqh, g_wqh); cudaGetSymbolAddress((void**)&p_wqm, g_wqm);
    cudaGetSymbolAddress((void**)&p_woh, g_woh); cudaGetSymbolAddress((void**)&p_wom, g_wom);

    cudaFuncSetAttribute(gemm_mma, cudaFuncAttributeMaxDynamicSharedMemorySize, GSMEM);

    ln_kernel<<<NPAD, 256>>>(x, norm_w, norm_b);
    wcvt_kernel<<<(NWQ + NWO + 255)/256, 256>>>(w_qkv, w_out);
    gemm_mma<<<dim3(QKVD/128, (NPAD+127)/128), 256, GSMEM>>>(
        p_ah, p_am, p_wqh, p_wqm, p_qkv, NPAD, QKVD, DIM, 0, nullptr, nullptr);
    landmark_kernel<<<dim3(MM, 2, LMCH), 512>>>();
    landmark2_kernel<<<dim3(MM, 2), 512>>>();
    pinv_kernel<<<HEADS, MM*MM>>>();
    attn1w1_kernel<<<dim3((NPAD+127)/128, HEADS), 128>>>();
    attn3a_kernel<<<dim3((NPAD+127)/128, HEADS), 128>>>();
    attn3b_kernel<<<dim3(MM, HEADS), 1024>>>();
    av_kernel<<<dim3(AVCH, HEADS), 544>>>();
    outh_kernel<<<dim3((NPAD+OTILE-1)/OTILE, HEADS), 256>>>(conv_w);
    gemm_mma<<<dim3(DIM/128, NTOK/128), 256, GSMEM>>>(
        p_oh + DIM, p_om + DIM, p_woh, p_wom,
        out, NTOK, DIM, DIM, 1, b_out, x);
    a3cvt_kernel<<<(HEADS*TPADN + 255)/256, 256>>>();
    attn_final_mma<<<dim3(TPADN/128, TPADN/128, HEADS), 256>>>(out + OUT1_SIZE);
}